// round 7
// baseline (speedup 1.0000x reference)
#include <cuda_runtime.h>
#include <cstdint>
#include <math.h>

// B=128, F=1024, W=32, H=64. Output = LSTM cell states [B, W, H] (fp32).
// Attention branch is dead code (softmax over size-1 axis == 1).

__device__ float g_Gx[4096u * 256u];   // 4 MB scratch: (b*32+t) x 4H gate pre-activations

__device__ __forceinline__ unsigned long long pack2(float x, float y) {
    unsigned long long r;
    asm("mov.b64 %0, {%1, %2};" : "=l"(r) : "f"(x), "f"(y));
    return r;
}
__device__ __forceinline__ void unpack2(unsigned long long v, float& x, float& y) {
    asm("mov.b64 {%0, %1}, %2;" : "=f"(x), "=f"(y) : "l"(v));
}
__device__ __forceinline__ void fma2(unsigned long long& d, unsigned long long a,
                                     unsigned long long b) {
    asm("fma.rn.f32x2 %0, %1, %2, %0;" : "+l"(d) : "l"(a), "l"(b));
}

// ---------------------------------------------------------------------------
// GEMM: Gx[m][n] = sum_k x[b(m)][k][t(m)] * Wx[k][n] + b_lstm[n]
//   m = b*32 + t  (M=4096), n in [0,256), K=1024.
// Grid (2, 64): N-tile 128, M-tile 64. 256 threads, thread tile 4m x (4x2)n.
// ---------------------------------------------------------------------------
__global__ __launch_bounds__(256) void gemm_kernel(const float* __restrict__ x,
                                                   const float* __restrict__ Wx,
                                                   const float* __restrict__ bias) {
    __shared__ float As[64][68];    // [k][m], padded
    __shared__ float Bs[64][128];   // [k][n]
    const int tid = threadIdx.x;
    const int n0 = blockIdx.x * 128;
    const int m0 = blockIdx.y * 64;
    const int b0 = m0 >> 5;         // covers batches b0, b0+1
    const int tx = tid & 15;        // n = n0 + tx*2 + np*32
    const int ty = tid >> 4;        // m = m0 + ty*4 + i

    unsigned long long acc[4][4];
#pragma unroll
    for (int i = 0; i < 4; i++)
#pragma unroll
        for (int j = 0; j < 4; j++) acc[i][j] = 0ull;

    for (int k0 = 0; k0 < 1024; k0 += 64) {
        // load A tile: 64k x 64m  (x[b][k][t], 32 contiguous t per (b,k) row)
#pragma unroll
        for (int i = 0; i < 4; i++) {
            int idx = tid + i * 256;          // 0..1023 float4s
            int r = idx >> 3;                 // bb*64 + k
            int q = idx & 7;                  // t quad
            int bb = r >> 6, k = r & 63;
            float4 v = *(const float4*)(x + (size_t)(b0 + bb) * 32768u
                                          + (size_t)(k0 + k) * 32u + q * 4);
            *(float4*)&As[k][bb * 32 + q * 4] = v;
        }
        // load B tile: 64k x 128n
#pragma unroll
        for (int i = 0; i < 8; i++) {
            int idx = tid + i * 256;          // 0..2047 float4s
            int k = idx >> 5;
            int q = idx & 31;
            *(float4*)&Bs[k][q * 4] =
                *(const float4*)(Wx + (size_t)(k0 + k) * 256u + n0 + q * 4);
        }
        __syncthreads();

#pragma unroll
        for (int k = 0; k < 64; k++) {
            float4 a = *(const float4*)&As[k][ty * 4];
            unsigned long long aa0 = pack2(a.x, a.x);
            unsigned long long aa1 = pack2(a.y, a.y);
            unsigned long long aa2 = pack2(a.z, a.z);
            unsigned long long aa3 = pack2(a.w, a.w);
            const float* brow = &Bs[k][tx * 2];
            unsigned long long bv0 = *(const unsigned long long*)(brow);
            unsigned long long bv1 = *(const unsigned long long*)(brow + 32);
            unsigned long long bv2 = *(const unsigned long long*)(brow + 64);
            unsigned long long bv3 = *(const unsigned long long*)(brow + 96);
            fma2(acc[0][0], aa0, bv0); fma2(acc[0][1], aa0, bv1);
            fma2(acc[0][2], aa0, bv2); fma2(acc[0][3], aa0, bv3);
            fma2(acc[1][0], aa1, bv0); fma2(acc[1][1], aa1, bv1);
            fma2(acc[1][2], aa1, bv2); fma2(acc[1][3], aa1, bv3);
            fma2(acc[2][0], aa2, bv0); fma2(acc[2][1], aa2, bv1);
            fma2(acc[2][2], aa2, bv2); fma2(acc[2][3], aa2, bv3);
            fma2(acc[3][0], aa3, bv0); fma2(acc[3][1], aa3, bv1);
            fma2(acc[3][2], aa3, bv2); fma2(acc[3][3], aa3, bv3);
        }
        __syncthreads();
    }

    // epilogue: add bias, store
#pragma unroll
    for (int i = 0; i < 4; i++) {
        int m = m0 + ty * 4 + i;
#pragma unroll
        for (int np = 0; np < 4; np++) {
            int n = n0 + tx * 2 + np * 32;
            float lo, hi;
            unpack2(acc[i][np], lo, hi);
            float2 r;
            r.x = lo + bias[n];
            r.y = hi + bias[n + 1];
            *(float2*)(g_Gx + (size_t)m * 256u + n) = r;
        }
    }
}

// ---------------------------------------------------------------------------
// Recurrence: one block per batch. Thread n owns gate column n (Wh[:,n] in
// registers). gates = Gx + h @ Wh; i,f,g,o = chunks of 64;
// c = sig(f)*c + sig(i)*tanh(g); h = sig(o)*tanh(c); out[b][t][:] = c.
// ---------------------------------------------------------------------------
__global__ __launch_bounds__(256) void lstm_kernel(const float* __restrict__ Wh,
                                                   float* __restrict__ out) {
    __shared__ float hs[64];
    __shared__ float gact[256];
    const int b = blockIdx.x;
    const int n = threadIdx.x;

    float w[64];
#pragma unroll
    for (int j = 0; j < 64; j++) w[j] = Wh[j * 256 + n];   // coalesced per j

    if (n < 64) hs[n] = 0.0f;
    float c = 0.0f;
    const float* gx = g_Gx + (size_t)b * 32u * 256u;
    const int chunk = n >> 6;
    __syncthreads();

    for (int t = 0; t < 32; t++) {
        float acc = gx[t * 256 + n];
#pragma unroll
        for (int j = 0; j < 64; j++) acc = fmaf(hs[j], w[j], acc);   // broadcast LDS

        float v;
        if (chunk == 2) v = tanhf(acc);
        else            v = 1.0f / (1.0f + __expf(-acc));
        gact[n] = v;
        __syncthreads();

        if (n < 64) {
            c = gact[64 + n] * c + gact[n] * gact[128 + n];
            hs[n] = gact[192 + n] * tanhf(c);
            out[(size_t)b * 2048u + (size_t)t * 64u + n] = c;
        }
        __syncthreads();
    }
}

extern "C" void kernel_launch(void* const* d_in, const int* in_sizes, int n_in,
                              void* d_out, int out_size) {
    const float* x      = (const float*)d_in[0];   // [128,1024,32]
    const float* Wx     = (const float*)d_in[6];   // [1024,256]
    const float* Wh     = (const float*)d_in[7];   // [64,256]
    const float* b_lstm = (const float*)d_in[8];   // [256]
    float* out = (float*)d_out;                    // [128,32,64]

    dim3 grid(2, 64);
    gemm_kernel<<<grid, 256>>>(x, Wx, b_lstm);
    lstm_kernel<<<128, 256>>>(Wh, out);
}

// round 9
// speedup vs baseline: 1.4625x; 1.4625x over previous
#include <cuda_runtime.h>
#include <cuda_bf16.h>
#include <cstdint>
#include <math.h>

// B=128, F=1024, W=32, H=64. Output = LSTM cell-state trajectory [B,W,H] fp32.
// Attention branch is dead code (softmax over a size-1 axis == 1).
//
// Gx = x^T-slices @ Wx via bf16x3 mma.sync GEMM (K expanded 1024 -> 3072:
// A chunks [hi,hi,lo] x B segs [hi,lo,hi]); then a latency-optimized LSTM.

__device__ __nv_bfloat16 g_A[4096u * 2048u];   // 16 MB: [m][0:1024)=hi, [1024:2048)=lo
__device__ __nv_bfloat16 g_B[256u * 3072u];    // 1.5 MB: [n][hi | lo | hi]
__device__ float         g_Gx[4096u * 256u];   // 4 MB gate pre-activations (no bias)

#define SWZ(o) ((o) ^ (((o) >> 3) & 0x70))

__device__ __forceinline__ uint32_t smem_u32(const void* p) {
    uint32_t a;
    asm("{ .reg .u64 t; cvta.to.shared.u64 t, %1; cvt.u32.u64 %0, t; }" : "=r"(a) : "l"(p));
    return a;
}
__device__ __forceinline__ void cp_async16(uint32_t dst, const void* src) {
    asm volatile("cp.async.cg.shared.global [%0], [%1], 16;" :: "r"(dst), "l"(src) : "memory");
}
__device__ __forceinline__ void cp_commit() { asm volatile("cp.async.commit_group;" ::: "memory"); }
template <int N> __device__ __forceinline__ void cp_wait() {
    asm volatile("cp.async.wait_group %0;" :: "n"(N) : "memory");
}
__device__ __forceinline__ void ldsm_x4(uint32_t* r, uint32_t addr) {
    asm volatile("ldmatrix.sync.aligned.m8n8.x4.shared.b16 {%0,%1,%2,%3}, [%4];"
                 : "=r"(r[0]), "=r"(r[1]), "=r"(r[2]), "=r"(r[3]) : "r"(addr));
}
__device__ __forceinline__ void mma_bf16(float* c, const uint32_t* a, uint32_t b0, uint32_t b1) {
    asm volatile(
        "mma.sync.aligned.m16n8k16.row.col.f32.bf16.bf16.f32 "
        "{%0,%1,%2,%3}, {%4,%5,%6,%7}, {%8,%9}, {%0,%1,%2,%3};"
        : "+f"(c[0]), "+f"(c[1]), "+f"(c[2]), "+f"(c[3])
        : "r"(a[0]), "r"(a[1]), "r"(a[2]), "r"(a[3]), "r"(b0), "r"(b1));
}
__device__ __forceinline__ unsigned long long pack2(float x, float y) {
    unsigned long long r; asm("mov.b64 %0, {%1, %2};" : "=l"(r) : "f"(x), "f"(y)); return r;
}
__device__ __forceinline__ void unpack2(unsigned long long v, float& x, float& y) {
    asm("mov.b64 {%0, %1}, %2;" : "=f"(x), "=f"(y) : "l"(v));
}
__device__ __forceinline__ void fma2(unsigned long long& d, unsigned long long a,
                                     unsigned long long b) {
    asm("fma.rn.f32x2 %0, %1, %2, %0;" : "+l"(d) : "l"(a), "l"(b));
}

// ---------- prep: x[B,F,W] -> A[m=(b,t)][f] split hi/lo ----------------------
__global__ __launch_bounds__(256) void prep_x(const float* __restrict__ x,
                                              __nv_bfloat16* __restrict__ A) {
    __shared__ float tile[32][33];
    const int tid = threadIdx.x;
    const int b = blockIdx.y, f0 = blockIdx.x * 32;
    const float* xb = x + (size_t)b * 32768u + (size_t)f0 * 32u;
#pragma unroll
    for (int i = 0; i < 4; i++) {
        int idx = tid + i * 256, r = idx >> 5, t = idx & 31;
        tile[r][t] = xb[r * 32 + t];
    }
    __syncthreads();
#pragma unroll
    for (int i = 0; i < 2; i++) {
        int idx = tid + i * 256, t = idx >> 4, fp = idx & 15;
        float v0 = tile[2 * fp][t], v1 = tile[2 * fp + 1][t];
        __nv_bfloat16 h0 = __float2bfloat16(v0), h1 = __float2bfloat16(v1);
        __nv_bfloat16 l0 = __float2bfloat16(v0 - __bfloat162float(h0));
        __nv_bfloat16 l1 = __float2bfloat16(v1 - __bfloat162float(h1));
        size_t row = (size_t)(b * 32 + t) * 2048u + f0 + 2 * fp;
        __nv_bfloat162 hh; hh.x = h0; hh.y = h1;
        __nv_bfloat162 ll; ll.x = l0; ll.y = l1;
        *(__nv_bfloat162*)(A + row)         = hh;
        *(__nv_bfloat162*)(A + row + 1024u) = ll;
    }
}

// ---------- prep: Wx[F,4H] -> B[n][hi|lo|hi] --------------------------------
__global__ __launch_bounds__(256) void prep_w(const float* __restrict__ Wx,
                                              __nv_bfloat16* __restrict__ Bo) {
    __shared__ float tile[32][33];
    const int tid = threadIdx.x;
    const int n0 = blockIdx.x * 32, k0 = blockIdx.y * 32;
#pragma unroll
    for (int i = 0; i < 4; i++) {
        int idx = tid + i * 256, r = idx >> 5, c = idx & 31;
        tile[r][c] = Wx[(size_t)(k0 + r) * 256u + n0 + c];
    }
    __syncthreads();
#pragma unroll
    for (int i = 0; i < 2; i++) {
        int idx = tid + i * 256, t = idx >> 4, fp = idx & 15;
        float v0 = tile[2 * fp][t], v1 = tile[2 * fp + 1][t];
        __nv_bfloat16 h0 = __float2bfloat16(v0), h1 = __float2bfloat16(v1);
        __nv_bfloat16 l0 = __float2bfloat16(v0 - __bfloat162float(h0));
        __nv_bfloat16 l1 = __float2bfloat16(v1 - __bfloat162float(h1));
        size_t row = (size_t)(n0 + t) * 3072u + k0 + 2 * fp;
        __nv_bfloat162 hh; hh.x = h0; hh.y = h1;
        __nv_bfloat162 ll; ll.x = l0; ll.y = l1;
        *(__nv_bfloat162*)(Bo + row)         = hh;
        *(__nv_bfloat162*)(Bo + row + 1024u) = ll;
        *(__nv_bfloat162*)(Bo + row + 2048u) = hh;
    }
}

// ---------- bf16x3 mma.sync GEMM: Gx[m][n], M=4096 N=256 K'=3072 ------------
// Grid (4 n-tiles, 32 m-tiles) = 128 CTAs. CTA tile 128m x 64n.
// 8 warps: wm = wid&3 (m sub 32), wn = wid>>2 (n sub 32).
__global__ __launch_bounds__(256) void gemm_kernel(const __nv_bfloat16* __restrict__ A,
                                                   const __nv_bfloat16* __restrict__ Bg,
                                                   float* __restrict__ Gx) {
    __shared__ __align__(1024) char sm[49152];   // A:2x16K, B:2x8K
    const int tid = threadIdx.x, lane = tid & 31, wid = tid >> 5;
    const int wm = wid & 3, wn = wid >> 2;
    const int n0 = blockIdx.x * 64, m0 = blockIdx.y * 128;
    const uint32_t smb = smem_u32(sm);
    // buffer byte offsets
    const uint32_t Aoff[2] = {0u, 24576u};
    const uint32_t Boff[2] = {16384u, 40960u};

    float acc[2][4][4];
#pragma unroll
    for (int i = 0; i < 2; i++)
#pragma unroll
        for (int j = 0; j < 4; j++)
#pragma unroll
            for (int q = 0; q < 4; q++) acc[i][j][q] = 0.0f;

    // ldmatrix address pre-compute (unswizzled offsets + fixed xor mask)
    const uint32_t xm = (uint32_t)((lane & 7) << 4);
    uint32_t oA[2], oB[2];
#pragma unroll
    for (int i = 0; i < 2; i++) {
        int rowA = wm * 32 + i * 16 + (lane & 15);
        oA[i] = (uint32_t)(rowA * 128 + (lane >> 4) * 16);
    }
#pragma unroll
    for (int jp = 0; jp < 2; jp++) {
        int rowB = wn * 32 + jp * 16 + ((lane & 16) ? 8 : 0) + (lane & 7);
        oB[jp] = (uint32_t)(rowB * 128 + ((lane & 8) ? 16 : 0));
    }

    auto load_chunk = [&](int c, int buf) {
        const int kA = (c < 16) ? c * 64 : (c < 32) ? (c - 16) * 64 : 1024 + (c - 32) * 64;
        const int kB = c * 64;
#pragma unroll
        for (int i = 0; i < 4; i++) {
            int cid = tid + i * 256, r = cid >> 3, q = cid & 7;
            const void* src = A + (size_t)(m0 + r) * 2048u + kA + q * 8;
            cp_async16(smb + Aoff[buf] + SWZ((uint32_t)(r * 128 + q * 16)), src);
        }
#pragma unroll
        for (int i = 0; i < 2; i++) {
            int cid = tid + i * 256, r = cid >> 3, q = cid & 7;
            const void* src = Bg + (size_t)(n0 + r) * 3072u + kB + q * 8;
            cp_async16(smb + Boff[buf] + SWZ((uint32_t)(r * 128 + q * 16)), src);
        }
        cp_commit();
    };

    load_chunk(0, 0);
    for (int c = 0; c < 48; c++) {
        const int buf = c & 1;
        if (c < 47) { load_chunk(c + 1, buf ^ 1); cp_wait<1>(); }
        else        { cp_wait<0>(); }
        __syncthreads();
        const uint32_t AS = smb + Aoff[buf], BS = smb + Boff[buf];
#pragma unroll
        for (int k16 = 0; k16 < 4; k16++) {
            const uint32_t bk = (uint32_t)(k16 * 32);
            uint32_t af[2][4], bf[2][4];
#pragma unroll
            for (int i = 0; i < 2; i++) ldsm_x4(af[i], AS + ((oA[i] + bk) ^ xm));
#pragma unroll
            for (int jp = 0; jp < 2; jp++) ldsm_x4(bf[jp], BS + ((oB[jp] + bk) ^ xm));
#pragma unroll
            for (int i = 0; i < 2; i++)
#pragma unroll
                for (int j = 0; j < 4; j++)
                    mma_bf16(acc[i][j], af[i], bf[j >> 1][(j & 1) * 2], bf[j >> 1][(j & 1) * 2 + 1]);
        }
        __syncthreads();
    }

    // epilogue
#pragma unroll
    for (int i = 0; i < 2; i++) {
        int mg = m0 + wm * 32 + i * 16 + (lane >> 2);
#pragma unroll
        for (int j = 0; j < 4; j++) {
            int ng = n0 + wn * 32 + j * 8 + 2 * (lane & 3);
            float2 lo; lo.x = acc[i][j][0]; lo.y = acc[i][j][1];
            float2 hi; hi.x = acc[i][j][2]; hi.y = acc[i][j][3];
            *(float2*)(Gx + (size_t)mg * 256u + ng)        = lo;
            *(float2*)(Gx + (size_t)(mg + 8) * 256u + ng)  = hi;
        }
    }
}

// ---------- LSTM recurrence --------------------------------------------------
__global__ __launch_bounds__(256) void lstm_kernel(const float* __restrict__ Wh,
                                                   const float* __restrict__ bias,
                                                   const float* __restrict__ Gx,
                                                   float* __restrict__ out) {
    __shared__ float gsum[8192];                 // 32 steps x 256 gates (+bias)
    __shared__ __align__(16) float hs[64];
    __shared__ float gact[256];
    const int b = blockIdx.x, n = threadIdx.x;

    unsigned long long w2[32];
#pragma unroll
    for (int j = 0; j < 32; j++)
        w2[j] = pack2(Wh[(2 * j) * 256 + n], Wh[(2 * j + 1) * 256 + n]);

    const float4* gp = (const float4*)(Gx + (size_t)b * 8192u);
#pragma unroll
    for (int i = 0; i < 8; i++) {
        int idx = n + i * 256;                   // float4 index over [t][n/4]
        float4 a = gp[idx];
        float4 bv = *(const float4*)(bias + (idx & 63) * 4);
        a.x += bv.x; a.y += bv.y; a.z += bv.z; a.w += bv.w;
        *(float4*)&gsum[idx * 4] = a;
    }
    if (n < 64) hs[n] = 0.0f;
    float cst = 0.0f;
    const int chunk = n >> 6;
    __syncthreads();

    for (int t = 0; t < 32; t++) {
        unsigned long long s0 = 0, s1 = 0, s2 = 0, s3 = 0;
        const ulonglong2* hv = (const ulonglong2*)hs;
#pragma unroll
        for (int j = 0; j < 16; j++) {           // covers hs[0..63]
            ulonglong2 h2 = hv[j];
            if (j & 1) { fma2(s2, h2.x, w2[2 * j]); fma2(s3, h2.y, w2[2 * j + 1]); }
            else       { fma2(s0, h2.x, w2[2 * j]); fma2(s1, h2.y, w2[2 * j + 1]); }
        }
        float x0, x1, y0, y1, z0, z1, u0, u1;
        unpack2(s0, x0, x1); unpack2(s1, y0, y1);
        unpack2(s2, z0, z1); unpack2(s3, u0, u1);
        float acc = gsum[t * 256 + n] + ((x0 + x1) + (y0 + y1)) + ((z0 + z1) + (u0 + u1));
        float v;
        if (chunk == 2) v = 2.0f / (1.0f + __expf(-2.0f * acc)) - 1.0f;   // tanh
        else            v = 1.0f / (1.0f + __expf(-acc));                  // sigmoid
        gact[n] = v;
        __syncthreads();
        if (n < 64) {
            cst = gact[64 + n] * cst + gact[n] * gact[128 + n];
            float th = 2.0f / (1.0f + __expf(-2.0f * cst)) - 1.0f;
            hs[n] = gact[192 + n] * th;
            out[(size_t)b * 2048u + (size_t)t * 64u + n] = cst;
        }
        __syncthreads();
    }
}

extern "C" void kernel_launch(void* const* d_in, const int* in_sizes, int n_in,
                              void* d_out, int out_size) {
    const float* x      = (const float*)d_in[0];   // [128,1024,32]
    const float* Wx     = (const float*)d_in[6];   // [1024,256]
    const float* Wh     = (const float*)d_in[7];   // [64,256]
    const float* b_lstm = (const float*)d_in[8];   // [256]
    float* out = (float*)d_out;                    // [128,32,64]

    __nv_bfloat16 *A, *Bg;
    float* Gx;
    cudaGetSymbolAddress((void**)&A, g_A);
    cudaGetSymbolAddress((void**)&Bg, g_B);
    cudaGetSymbolAddress((void**)&Gx, g_Gx);

    prep_x<<<dim3(32, 128), 256>>>(x, A);
    prep_w<<<dim3(8, 32), 256>>>(Wx, Bg);
    gemm_kernel<<<dim3(4, 32), 256>>>(A, Bg, Gx);
    lstm_kernel<<<128, 256>>>(Wh, b_lstm, Gx, out);
}